// round 4
// baseline (speedup 1.0000x reference)
#include <cuda_runtime.h>
#include <cuda_bf16.h>
#include <cstdint>
#include <cstddef>

#define BATCH 2
#define DIM 128
#define CIN 64
#define COUT 64
#define HH 96
#define WW 96
#define HW (HH*WW)           // 9216
#define HEADS 8
#define CH 16
#define DEPTH 4
#define NIDX (BATCH*HH)      // 192 (b,y) slots for bn partials

// ---------------- scratch (device globals) ----------------
__device__ __align__(16) float g_t  [BATCH*DIM*HW];   // conv out (fp32, pre-BN)
__device__ __align__(16) float g_bn [BATCH*DIM*HW];   // bn+relu out (fp32 residual)
__device__ __align__(16) float g_qkv[BATCH*3*DIM*HW];
__device__ __align__(16) uint2 g_hsp[BATCH*64*HW];    // split h   (conv / out-proj B)
__device__ __align__(16) uint2 g_qsp[BATCH*64*HW];    // split bn  (qkv B)
__device__ __align__(16) uint2 g_asp[BATCH*64*HW];    // split att (fc B)
__device__ float g_ps[DIM*NIDX];                      // bn partial sums
__device__ float g_pq[DIM*NIDX];                      // bn partial sumsq
__device__ float g_mean[DIM];
__device__ float g_rstd[DIM];
// packed split weights: uint2 {hi,lo}, layout [K/2][M]
__device__ uint2 g_cw[DEPTH*9*64*DIM];   // [d][tap][ic2][oc]
__device__ uint2 g_qw[DEPTH*64*3*DIM];
__device__ uint2 g_fw[DEPTH*64*DIM];
__device__ uint2 g_wi[32*DIM];
__device__ uint2 g_wo[64*COUT];

__device__ __forceinline__ void split2(float x0, float x1, uint32_t& hi, uint32_t& lo)
{
    __nv_bfloat16 h0 = __float2bfloat16(x0);
    __nv_bfloat16 h1 = __float2bfloat16(x1);
    float l0f = x0 - __bfloat162float(h0);
    float l1f = x1 - __bfloat162float(h1);
    __nv_bfloat162 hh = __halves2bfloat162(h0, h1);
    __nv_bfloat162 ll = __halves2bfloat162(__float2bfloat16(l0f), __float2bfloat16(l1f));
    hi = *reinterpret_cast<uint32_t*>(&hh);
    lo = *reinterpret_cast<uint32_t*>(&ll);
}

__device__ __forceinline__ void mma_bf16(float c[4],
    uint32_t a0, uint32_t a1, uint32_t a2, uint32_t a3, uint32_t b0, uint32_t b1)
{
    asm volatile(
        "mma.sync.aligned.m16n8k16.row.col.f32.bf16.bf16.f32 "
        "{%0,%1,%2,%3}, {%4,%5,%6,%7}, {%8,%9}, {%0,%1,%2,%3};"
        : "+f"(c[0]), "+f"(c[1]), "+f"(c[2]), "+f"(c[3])
        : "r"(a0), "r"(a1), "r"(a2), "r"(a3), "r"(b0), "r"(b1));
}

// ---------------- unified weight prep (single launch) ----------------
#define NC (DEPTH*9*64*DIM)      // 294912
#define NQ (DEPTH*64*3*DIM)      // 98304
#define NF (DEPTH*64*DIM)        // 32768
#define NI (32*DIM)              // 4096
#define NO (64*COUT)             // 4096
__global__ void prep_all(const float* __restrict__ conv_w, const float* __restrict__ qkv_w,
                         const float* __restrict__ fc_w, const float* __restrict__ w_in,
                         const float* __restrict__ w_out)
{
    int i = blockIdx.x*256 + threadIdx.x;
    float x0, x1; uint2* dst;
    if (i < NC) {
        int oc = i & 127; int r = i >> 7; int ic2 = r & 63; r >>= 6;
        int tap = r % 9, d = r / 9;
        size_t base = ((size_t)(d*DIM + oc)*DIM + 2*ic2)*9 + tap;
        x0 = conv_w[base]; x1 = conv_w[base + 9]; dst = &g_cw[i];
    } else if (i < NC+NQ) {
        int j = i - NC; int d = j / (64*384); int l = j % (64*384);
        int k2 = l / 384, m = l % 384;
        x0 = qkv_w[((size_t)d*384 + m)*DIM + 2*k2];
        x1 = qkv_w[((size_t)d*384 + m)*DIM + 2*k2 + 1];
        dst = &g_qw[j];
    } else if (i < NC+NQ+NF) {
        int j = i - NC - NQ; int d = j / (64*DIM); int l = j % (64*DIM);
        int k2 = l / DIM, m = l % DIM;
        x0 = fc_w[((size_t)d*DIM + m)*DIM + 2*k2];
        x1 = fc_w[((size_t)d*DIM + m)*DIM + 2*k2 + 1];
        dst = &g_fw[j];
    } else if (i < NC+NQ+NF+NI) {
        int j = i - NC - NQ - NF; int k2 = j / DIM, m = j % DIM;
        x0 = w_in[(size_t)m*CIN + 2*k2]; x1 = w_in[(size_t)m*CIN + 2*k2 + 1];
        dst = &g_wi[j];
    } else if (i < NC+NQ+NF+NI+NO) {
        int j = i - NC - NQ - NF - NI; int k2 = j / COUT, m = j % COUT;
        x0 = w_out[(size_t)m*DIM + 2*k2]; x1 = w_out[(size_t)m*DIM + 2*k2 + 1];
        dst = &g_wo[j];
    } else return;
    uint32_t hi, lo; split2(x0, x1, hi, lo);
    *dst = make_uint2(hi, lo);
}

// ---------------- unified bf16x3 GEMM ----------------
// W: [K/2][Mtot] uint2. B: pre-split uint2 [K/2][HW] (bsplit=1) or fp32 [K][HW].
// Out: fp32 [Mtot][HW] (osplit=0) or split uint2 [Mtot/2][HW] (osplit=1).
__global__ void gemm_bf3(const uint2* __restrict__ W, const void* __restrict__ Bin, int bsplit,
                         const float* __restrict__ bias, const float* __restrict__ res,
                         void* __restrict__ Out, int osplit, int Mtot, int K)
{
    const int b  = blockIdx.z;
    const int m0 = blockIdx.y * 64, n0 = blockIdx.x * 64;

    __shared__ uint32_t As[2][8][72];
    __shared__ uint32_t Bs[2][8][72];

    const int tid  = threadIdx.x;
    const int warp = tid >> 5, lane = tid & 31;
    const int wm = warp >> 1, wn = warp & 1;
    const int g = lane >> 2, t = lane & 3;

    float acc[4][4] = {};

    for (int k0 = 0; k0 < K; k0 += 16) {
        #pragma unroll
        for (int i = tid; i < 512; i += 256) {
            int tt = i >> 6, m = i & 63;
            uint2 w = W[(size_t)(k0/2 + tt)*Mtot + m0 + m];
            As[0][tt][m] = w.x; As[1][tt][m] = w.y;
        }
        if (bsplit) {
            const uint2* Bsp = (const uint2*)Bin + (size_t)b*(K/2)*HW;
            #pragma unroll
            for (int i = tid; i < 512; i += 256) {
                int tt = i >> 6, n = i & 63;
                uint2 v = Bsp[(size_t)(k0/2 + tt)*HW + n0 + n];
                Bs[0][tt][n] = v.x; Bs[1][tt][n] = v.y;
            }
        } else {
            const float* Bf = (const float*)Bin + (size_t)b*K*HW;
            #pragma unroll
            for (int i = tid; i < 512; i += 256) {
                int tt = i >> 6, n = i & 63;
                const float* xp = &Bf[(size_t)(k0 + 2*tt)*HW + n0 + n];
                uint32_t hi, lo; split2(xp[0], xp[HW], hi, lo);
                Bs[0][tt][n] = hi; Bs[1][tt][n] = lo;
            }
        }
        __syncthreads();

        const int mrow = wm*16 + g;
        uint32_t ah0 = As[0][t  ][mrow], ah1 = As[0][t  ][mrow+8];
        uint32_t ah2 = As[0][t+4][mrow], ah3 = As[0][t+4][mrow+8];
        uint32_t al0 = As[1][t  ][mrow], al1 = As[1][t  ][mrow+8];
        uint32_t al2 = As[1][t+4][mrow], al3 = As[1][t+4][mrow+8];
        #pragma unroll
        for (int nt = 0; nt < 4; nt++) {
            int col = wn*32 + nt*8 + g;
            uint32_t bh0 = Bs[0][t][col], bh1 = Bs[0][t+4][col];
            uint32_t bl0 = Bs[1][t][col], bl1 = Bs[1][t+4][col];
            mma_bf16(acc[nt], ah0, ah1, ah2, ah3, bh0, bh1);
            mma_bf16(acc[nt], ah0, ah1, ah2, ah3, bl0, bl1);
            mma_bf16(acc[nt], al0, al1, al2, al3, bh0, bh1);
        }
        __syncthreads();
    }

    const int row0 = m0 + wm*16 + g;
    const float b0v = bias ? bias[row0]     : 0.f;
    const float b1v = bias ? bias[row0 + 8] : 0.f;
    const float* Rb = res ? res + (size_t)b*Mtot*HW : nullptr;

    #pragma unroll
    for (int nt = 0; nt < 4; nt++) {
        int col = n0 + wn*32 + nt*8 + 2*t;
        float v00 = acc[nt][0] + b0v, v01 = acc[nt][1] + b0v;
        float v10 = acc[nt][2] + b1v, v11 = acc[nt][3] + b1v;
        if (Rb) {
            float2 r0 = *(const float2*)&Rb[(size_t)row0*HW + col];
            float2 r1 = *(const float2*)&Rb[(size_t)(row0+8)*HW + col];
            v00 += r0.x; v01 += r0.y; v10 += r1.x; v11 += r1.y;
        }
        if (!osplit) {
            float* Yb = (float*)Out + (size_t)b*Mtot*HW;
            *(float2*)&Yb[(size_t)row0*HW + col]     = make_float2(v00, v01);
            *(float2*)&Yb[(size_t)(row0+8)*HW + col] = make_float2(v10, v11);
        } else {
            // pair rows (2c, 2c+1): partner row differs by 1 <=> lane ^ 4
            float p00 = __shfl_xor_sync(0xffffffffu, v00, 4);
            float p01 = __shfl_xor_sync(0xffffffffu, v01, 4);
            float p10 = __shfl_xor_sync(0xffffffffu, v10, 4);
            float p11 = __shfl_xor_sync(0xffffffffu, v11, 4);
            if (!(g & 1)) {
                uint2* Osp = (uint2*)Out + (size_t)b*(Mtot/2)*HW;
                int c2 = row0 >> 1;
                uint32_t h0,l0,h1,l1;
                split2(v00, p00, h0, l0); split2(v01, p01, h1, l1);
                *(uint4*)&Osp[(size_t)c2*HW + col] = make_uint4(h0,l0,h1,l1);
                split2(v10, p10, h0, l0); split2(v11, p11, h1, l1);
                *(uint4*)&Osp[(size_t)(c2+4)*HW + col] = make_uint4(h0,l0,h1,l1);
            }
        }
    }
}

// ---------------- dilated 3x3 conv (bf16x3, split-B input, fp32 out + bn partials) ----------------
__global__ void conv3x3_bf3(const uint2* __restrict__ Bsp, const uint2* __restrict__ CW,
                            const float* __restrict__ bias, float* __restrict__ Y, int d)
{
    const int m0 = blockIdx.x * 64;
    const int y  = blockIdx.y;
    const int b  = blockIdx.z;
    const uint2* Xb = Bsp + (size_t)b*64*HW;

    __shared__ uint32_t As[2][8][72];
    __shared__ uint32_t Bs[2][8][104];
    __shared__ float sS[2][64], sQ[2][64];

    const int tid  = threadIdx.x;
    const int warp = tid >> 5, lane = tid & 31;
    const int wm = warp >> 1, wn = warp & 1;
    const int g = lane >> 2, t = lane & 3;

    float acc[6][4] = {};

    for (int tap = 0; tap < 9; tap++) {
        const int dy = tap/3 - 1, dx = tap%3 - 1;
        const int yy = y + dy*d;
        if (yy < 0 || yy >= HH) continue;
        const int xs = dx*d;
        const uint2* Xrow0 = Xb + (size_t)yy*WW;
        const uint2* Wt = CW + (size_t)tap*64*DIM;

        for (int ic0 = 0; ic0 < DIM; ic0 += 16) {
            #pragma unroll
            for (int i = tid; i < 512; i += 256) {
                int tt = i >> 6, m = i & 63;
                uint2 w = Wt[(size_t)(ic0/2 + tt)*DIM + m0 + m];
                As[0][tt][m] = w.x; As[1][tt][m] = w.y;
            }
            #pragma unroll
            for (int i = tid; i < 768; i += 256) {
                int tt = i / 96, n = i % 96;
                int xx = n + xs;
                uint2 v = make_uint2(0u, 0u);
                if (xx >= 0 && xx < WW)
                    v = Xrow0[(size_t)(ic0/2 + tt)*HW + xx];
                Bs[0][tt][n] = v.x; Bs[1][tt][n] = v.y;
            }
            __syncthreads();

            const int mrow = wm*16 + g;
            uint32_t ah0 = As[0][t  ][mrow], ah1 = As[0][t  ][mrow+8];
            uint32_t ah2 = As[0][t+4][mrow], ah3 = As[0][t+4][mrow+8];
            uint32_t al0 = As[1][t  ][mrow], al1 = As[1][t  ][mrow+8];
            uint32_t al2 = As[1][t+4][mrow], al3 = As[1][t+4][mrow+8];
            #pragma unroll
            for (int nt = 0; nt < 6; nt++) {
                int col = wn*48 + nt*8 + g;
                uint32_t bh0 = Bs[0][t][col], bh1 = Bs[0][t+4][col];
                uint32_t bl0 = Bs[1][t][col], bl1 = Bs[1][t+4][col];
                mma_bf16(acc[nt], ah0, ah1, ah2, ah3, bh0, bh1);
                mma_bf16(acc[nt], ah0, ah1, ah2, ah3, bl0, bl1);
                mma_bf16(acc[nt], al0, al1, al2, al3, bh0, bh1);
            }
            __syncthreads();
        }
    }

    float* Yb = Y + (size_t)b*DIM*HW + (size_t)y*WW;
    const int row0 = m0 + wm*16 + g;
    const float b0v = bias[row0], b1v = bias[row0 + 8];
    float s0 = 0.f, q0 = 0.f, s1 = 0.f, q1 = 0.f;
    #pragma unroll
    for (int nt = 0; nt < 6; nt++) {
        int col = wn*48 + nt*8 + 2*t;
        float v00 = acc[nt][0] + b0v, v01 = acc[nt][1] + b0v;
        float v10 = acc[nt][2] + b1v, v11 = acc[nt][3] + b1v;
        *(float2*)&Yb[(size_t)row0*HW + col]     = make_float2(v00, v01);
        *(float2*)&Yb[(size_t)(row0+8)*HW + col] = make_float2(v10, v11);
        s0 += v00 + v01; q0 += v00*v00 + v01*v01;
        s1 += v10 + v11; q1 += v10*v10 + v11*v11;
    }
    // reduce over t (lane bits 0,1)
    #pragma unroll
    for (int o = 1; o <= 2; o <<= 1) {
        s0 += __shfl_xor_sync(0xffffffffu, s0, o);
        q0 += __shfl_xor_sync(0xffffffffu, q0, o);
        s1 += __shfl_xor_sync(0xffffffffu, s1, o);
        q1 += __shfl_xor_sync(0xffffffffu, q1, o);
    }
    if (t == 0) {
        int lr = wm*16 + g;
        sS[wn][lr] = s0; sQ[wn][lr] = q0;
        sS[wn][lr+8] = s1; sQ[wn][lr+8] = q1;
    }
    __syncthreads();
    if (tid < 64) {
        int idx = b*HH + y;
        g_ps[(size_t)(m0+tid)*NIDX + idx] = sS[0][tid] + sS[1][tid];
        g_pq[(size_t)(m0+tid)*NIDX + idx] = sQ[0][tid] + sQ[1][tid];
    }
}

// ---------------- bn finalize (one small block) ----------------
__global__ void bn_finalize()
{
    int c = threadIdx.x;
    float s = 0.f, q = 0.f;
    #pragma unroll 4
    for (int i = 0; i < NIDX; i++) {
        s += g_ps[(size_t)c*NIDX + i];
        q += g_pq[(size_t)c*NIDX + i];
    }
    const float invN = 1.f / (BATCH*HW);
    float m = s * invN;
    float var = q * invN - m*m;
    g_mean[c] = m;
    g_rstd[c] = rsqrtf(var + 1e-5f);
}

// ---------------- bn apply + relu: writes fp32 residual + split qkv-input ----------------
__global__ void bn_apply_relu(const float* __restrict__ X, const float* __restrict__ gam,
                              const float* __restrict__ beta, float* __restrict__ Yf,
                              uint2* __restrict__ Ysp)
{
    const int b = blockIdx.y;
    int i = blockIdx.x*256 + threadIdx.x;       // over 64 * HW/4
    int c2 = i / (HW/4);
    int p  = (i - c2*(HW/4)) * 4;
    const float* Xb = X + (size_t)b*DIM*HW;
    float* Yb = Yf + (size_t)b*DIM*HW;
    uint2* Sb = Ysp + (size_t)b*64*HW;

    int c0 = 2*c2, c1 = 2*c2 + 1;
    float m0 = g_mean[c0], r0 = g_rstd[c0], ga0 = gam[c0], be0 = beta[c0];
    float m1 = g_mean[c1], r1 = g_rstd[c1], ga1 = gam[c1], be1 = beta[c1];

    float4 a = *(const float4*)&Xb[(size_t)c0*HW + p];
    float4 c = *(const float4*)&Xb[(size_t)c1*HW + p];
    float y0x = fmaxf((a.x-m0)*r0*ga0+be0, 0.f), y0y = fmaxf((a.y-m0)*r0*ga0+be0, 0.f);
    float y0z = fmaxf((a.z-m0)*r0*ga0+be0, 0.f), y0w = fmaxf((a.w-m0)*r0*ga0+be0, 0.f);
    float y1x = fmaxf((c.x-m1)*r1*ga1+be1, 0.f), y1y = fmaxf((c.y-m1)*r1*ga1+be1, 0.f);
    float y1z = fmaxf((c.z-m1)*r1*ga1+be1, 0.f), y1w = fmaxf((c.w-m1)*r1*ga1+be1, 0.f);

    *(float4*)&Yb[(size_t)c0*HW + p] = make_float4(y0x, y0y, y0z, y0w);
    *(float4*)&Yb[(size_t)c1*HW + p] = make_float4(y1x, y1y, y1z, y1w);

    uint32_t h0,l0,h1,l1,h2,l2,h3,l3;
    split2(y0x, y1x, h0, l0); split2(y0y, y1y, h1, l1);
    split2(y0z, y1z, h2, l2); split2(y0w, y1w, h3, l3);
    uint4* dst = (uint4*)&Sb[(size_t)c2*HW + p];
    dst[0] = make_uint4(h0, l0, h1, l1);
    dst[1] = make_uint4(h2, l2, h3, l3);
}

// ---------------- local channel self-attention (split epilogue) ----------------
__global__ void attn_core(const float* __restrict__ QKV, uint2* __restrict__ OUT)
{
    const int b = blockIdx.z, h = blockIdx.y;
    const int p0 = blockIdx.x * 32;
    const int y  = p0 / WW, x0 = p0 % WW;
    const float* Qb = QKV + ((size_t)b*3*DIM + h*CH)*HW;
    const float* Kb = Qb + (size_t)DIM*HW;
    const float* Vb = Qb + (size_t)2*DIM*HW;

    __shared__ float qs[CH][3][34];
    __shared__ float ks[CH][3][34];
    __shared__ float vs[CH][3][34];
    __shared__ float sato[CH][33];

    const int tid = threadIdx.y*32 + threadIdx.x;
    for (int i = tid; i < CH*3*34; i += 512) {
        int xi = i % 34; int rr = i / 34; int yi = rr % 3; int c = rr / 3;
        int yy = y + yi - 1, xx = x0 + xi - 1;
        bool ok = (yy >= 0 && yy < HH && xx >= 0 && xx < WW);
        int o = c*HW + yy*WW + xx;
        qs[c][yi][xi] = ok ? Qb[o] : 0.f;
        ks[c][yi][xi] = ok ? Kb[o] : 0.f;
        vs[c][yi][xi] = ok ? Vb[o] : 0.f;
    }
    __syncthreads();

    const int n = threadIdx.y, lx = threadIdx.x;
    float qr[9];
    #pragma unroll
    for (int t = 0; t < 9; t++) qr[t] = qs[n][t/3][lx + t%3] * 0.25f;

    float dots[CH], vsum[CH];
    #pragma unroll
    for (int m = 0; m < CH; m++) {
        float dv = 0.f, sv = 0.f;
        #pragma unroll
        for (int t = 0; t < 9; t++) {
            dv += qr[t] * ks[m][t/3][lx + t%3];
            sv += vs[m][t/3][lx + t%3];
        }
        dots[m] = dv; vsum[m] = sv;
    }
    float mx = dots[0];
    #pragma unroll
    for (int m = 1; m < CH; m++) mx = fmaxf(mx, dots[m]);
    float s = 0.f;
    #pragma unroll
    for (int m = 0; m < CH; m++) { dots[m] = __expf(dots[m]-mx); s += dots[m]; }
    float o = 0.f;
    #pragma unroll
    for (int m = 0; m < CH; m++) o += dots[m]*vsum[m];
    sato[n][lx] = o / s;
    __syncthreads();

    if (n < 8) {
        float v0 = sato[2*n][lx], v1 = sato[2*n+1][lx];
        uint32_t hi, lo; split2(v0, v1, hi, lo);
        OUT[(size_t)b*64*HW + (size_t)(h*8 + n)*HW + p0 + lx] = make_uint2(hi, lo);
    }
}

// ---------------- host orchestration ----------------
extern "C" void kernel_launch(void* const* d_in, const int* in_sizes, int n_in,
                              void* d_out, int out_size)
{
    const float* x      = (const float*)d_in[0];
    const float* w_in   = (const float*)d_in[1];
    const float* b_in   = (const float*)d_in[2];
    const float* conv_w = (const float*)d_in[3];
    const float* conv_b = (const float*)d_in[4];
    const float* bn_g   = (const float*)d_in[5];
    const float* bn_b   = (const float*)d_in[6];
    const float* qkv_w  = (const float*)d_in[7];
    const float* fc_w   = (const float*)d_in[8];
    const float* fc_b   = (const float*)d_in[9];
    const float* w_out  = (const float*)d_in[10];
    const float* b_out  = (const float*)d_in[11];
    float* out = (float*)d_out;

    float *p_t, *p_bn, *p_qkv;
    uint2 *p_hsp, *p_qsp, *p_asp, *p_cw, *p_qw, *p_fw, *p_wi, *p_wo;
    cudaGetSymbolAddress((void**)&p_t,    g_t);
    cudaGetSymbolAddress((void**)&p_bn,   g_bn);
    cudaGetSymbolAddress((void**)&p_qkv,  g_qkv);
    cudaGetSymbolAddress((void**)&p_hsp,  g_hsp);
    cudaGetSymbolAddress((void**)&p_qsp,  g_qsp);
    cudaGetSymbolAddress((void**)&p_asp,  g_asp);
    cudaGetSymbolAddress((void**)&p_cw,   g_cw);
    cudaGetSymbolAddress((void**)&p_qw,   g_qw);
    cudaGetSymbolAddress((void**)&p_fw,   g_fw);
    cudaGetSymbolAddress((void**)&p_wi,   g_wi);
    cudaGetSymbolAddress((void**)&p_wo,   g_wo);

    // weight prep (single launch)
    prep_all<<<(NC+NQ+NF+NI+NO + 255)/256, 256>>>(conv_w, qkv_w, fc_w, w_in, w_out);

    // input projection 64 -> 128, split output into g_hsp
    {
        dim3 g(HW/64, DIM/64, BATCH);
        gemm_bf3<<<g, 256>>>(p_wi, x, 0, b_in, nullptr, p_hsp, 1, DIM, CIN);
    }

    for (int i = 0; i < DEPTH; i++) {
        const int d = 1 << i;
        {   // dilated conv (split B), fp32 out + bn partials
            dim3 g(2, HH, BATCH);
            conv3x3_bf3<<<g, 256>>>(p_hsp, p_cw + (size_t)i*9*64*DIM,
                                    conv_b + i*DIM, p_t, d);
        }
        bn_finalize<<<1, DIM>>>();
        {   // bn apply + relu -> fp32 residual + split qkv input
            dim3 g((64*HW/4)/256, BATCH);
            bn_apply_relu<<<g, 256>>>(p_t, bn_g + i*DIM, bn_b + i*DIM, p_bn, p_qsp);
        }
        {   // qkv: 128 -> 384 (split B, fp32 out)
            dim3 g(HW/64, (3*DIM)/64, BATCH);
            gemm_bf3<<<g, 256>>>(p_qw + (size_t)i*64*3*DIM, p_qsp, 1, nullptr, nullptr,
                                 p_qkv, 0, 3*DIM, DIM);
        }
        {   // attention -> split att
            dim3 g(HW/32, HEADS, BATCH);
            dim3 blk(32, CH);
            attn_core<<<g, blk>>>(p_qkv, p_asp);
        }
        {   // fc + bias + residual(bn out) -> split h
            dim3 g(HW/64, DIM/64, BATCH);
            gemm_bf3<<<g, 256>>>(p_fw + (size_t)i*64*DIM, p_asp, 1, fc_b + i*DIM, p_bn,
                                 p_hsp, 1, DIM, DIM);
        }
    }

    // output projection 128 -> 64 (split B, fp32 out)
    {
        dim3 g(HW/64, COUT/64, BATCH);
        gemm_bf3<<<g, 256>>>(p_wo, p_hsp, 1, b_out, nullptr, out, 0, COUT, DIM);
    }
}

// round 5
// speedup vs baseline: 1.3485x; 1.3485x over previous
#include <cuda_runtime.h>
#include <cuda_bf16.h>
#include <cstdint>
#include <cstddef>

#define BATCH 2
#define DIM 128
#define CIN 64
#define COUT 64
#define HH 96
#define WW 96
#define HW (HH*WW)           // 9216
#define HEADS 8
#define CH 16
#define DEPTH 4
#define NIDX (BATCH*HH)      // 192 (b,y) slots for bn partials

// ---------------- scratch (device globals) ----------------
__device__ __align__(16) float g_t  [BATCH*DIM*HW];   // conv out (fp32, pre-BN)
__device__ __align__(16) float g_bn [BATCH*DIM*HW];   // bn+relu out (fp32 residual)
__device__ __align__(16) float g_qkv[BATCH*3*DIM*HW];
__device__ __align__(16) uint2 g_hsp[BATCH*64*HW];    // split h   (conv / out-proj B)
__device__ __align__(16) uint2 g_qsp[BATCH*64*HW];    // split bn  (qkv B)
__device__ __align__(16) uint2 g_asp[BATCH*64*HW];    // split att (fc B)
__device__ float g_ps[DIM*NIDX];                      // bn partial sums
__device__ float g_pq[DIM*NIDX];                      // bn partial sumsq
__device__ float g_mean[DIM];
__device__ float g_rstd[DIM];
// packed split weights: uint2 {hi,lo}, layout [K/2][M]
__device__ uint2 g_cw[DEPTH*9*64*DIM];   // [d][tap][ic2][oc]
__device__ uint2 g_qw[DEPTH*64*3*DIM];
__device__ uint2 g_fw[DEPTH*64*DIM];
__device__ uint2 g_wi[32*DIM];
__device__ uint2 g_wo[64*COUT];

__device__ __forceinline__ void split2(float x0, float x1, uint32_t& hi, uint32_t& lo)
{
    __nv_bfloat16 h0 = __float2bfloat16(x0);
    __nv_bfloat16 h1 = __float2bfloat16(x1);
    float l0f = x0 - __bfloat162float(h0);
    float l1f = x1 - __bfloat162float(h1);
    __nv_bfloat162 hh = __halves2bfloat162(h0, h1);
    __nv_bfloat162 ll = __halves2bfloat162(__float2bfloat16(l0f), __float2bfloat16(l1f));
    hi = *reinterpret_cast<uint32_t*>(&hh);
    lo = *reinterpret_cast<uint32_t*>(&ll);
}

__device__ __forceinline__ void mma_bf16(float c[4],
    uint32_t a0, uint32_t a1, uint32_t a2, uint32_t a3, uint32_t b0, uint32_t b1)
{
    asm volatile(
        "mma.sync.aligned.m16n8k16.row.col.f32.bf16.bf16.f32 "
        "{%0,%1,%2,%3}, {%4,%5,%6,%7}, {%8,%9}, {%0,%1,%2,%3};"
        : "+f"(c[0]), "+f"(c[1]), "+f"(c[2]), "+f"(c[3])
        : "r"(a0), "r"(a1), "r"(a2), "r"(a3), "r"(b0), "r"(b1));
}

// ---------------- unified weight prep (single launch) ----------------
#define NC (DEPTH*9*64*DIM)      // 294912
#define NQ (DEPTH*64*3*DIM)      // 98304
#define NF (DEPTH*64*DIM)        // 32768
#define NI (32*DIM)              // 4096
#define NO (64*COUT)             // 4096
__global__ void prep_all(const float* __restrict__ conv_w, const float* __restrict__ qkv_w,
                         const float* __restrict__ fc_w, const float* __restrict__ w_in,
                         const float* __restrict__ w_out)
{
    int i = blockIdx.x*256 + threadIdx.x;
    float x0, x1; uint2* dst;
    if (i < NC) {
        int oc = i & 127; int r = i >> 7; int ic2 = r & 63; r >>= 6;
        int tap = r % 9, d = r / 9;
        size_t base = ((size_t)(d*DIM + oc)*DIM + 2*ic2)*9 + tap;
        x0 = conv_w[base]; x1 = conv_w[base + 9]; dst = &g_cw[i];
    } else if (i < NC+NQ) {
        int j = i - NC; int d = j / (64*384); int l = j % (64*384);
        int k2 = l / 384, m = l % 384;
        x0 = qkv_w[((size_t)d*384 + m)*DIM + 2*k2];
        x1 = qkv_w[((size_t)d*384 + m)*DIM + 2*k2 + 1];
        dst = &g_qw[j];
    } else if (i < NC+NQ+NF) {
        int j = i - NC - NQ; int d = j / (64*DIM); int l = j % (64*DIM);
        int k2 = l / DIM, m = l % DIM;
        x0 = fc_w[((size_t)d*DIM + m)*DIM + 2*k2];
        x1 = fc_w[((size_t)d*DIM + m)*DIM + 2*k2 + 1];
        dst = &g_fw[j];
    } else if (i < NC+NQ+NF+NI) {
        int j = i - NC - NQ - NF; int k2 = j / DIM, m = j % DIM;
        x0 = w_in[(size_t)m*CIN + 2*k2]; x1 = w_in[(size_t)m*CIN + 2*k2 + 1];
        dst = &g_wi[j];
    } else if (i < NC+NQ+NF+NI+NO) {
        int j = i - NC - NQ - NF - NI; int k2 = j / COUT, m = j % COUT;
        x0 = w_out[(size_t)m*DIM + 2*k2]; x1 = w_out[(size_t)m*DIM + 2*k2 + 1];
        dst = &g_wo[j];
    } else return;
    uint32_t hi, lo; split2(x0, x1, hi, lo);
    *dst = make_uint2(hi, lo);
}

// ---------------- unified bf16x3 GEMM (2-stage pipelined) ----------------
// W: [K/2][Mtot] uint2. B: pre-split uint2 [K/2][HW] (bsplit=1) or fp32 [K][HW].
// Out: fp32 [Mtot][HW] (osplit=0) or split uint2 [Mtot/2][HW] (osplit=1).
__global__ void gemm_bf3(const uint2* __restrict__ W, const void* __restrict__ Bin, int bsplit,
                         const float* __restrict__ bias, const float* __restrict__ res,
                         void* __restrict__ Out, int osplit, int Mtot, int K)
{
    const int b  = blockIdx.z;
    const int m0 = blockIdx.y * 64, n0 = blockIdx.x * 64;

    __shared__ uint32_t As[2][2][8][72];
    __shared__ uint32_t Bs[2][2][8][72];

    const int tid  = threadIdx.x;
    const int warp = tid >> 5, lane = tid & 31;
    const int wm = warp >> 1, wn = warp & 1;
    const int g = lane >> 2, t = lane & 3;
    const int tt0 = tid >> 6, mcol = tid & 63;

    const uint2* Bsp = (const uint2*)Bin + (size_t)b*(K/2)*HW;
    const float* Bf  = (const float*)Bin + (size_t)b*K*HW;

    const int nk = K/16;
    float acc[4][4] = {};

    uint2 ra0, ra1, rb0, rb1;
    float f00 = 0.f, f01 = 0.f, f10 = 0.f, f11 = 0.f;

#define G_LOAD(c) do { \
        ra0 = W[(size_t)((c)*8 + tt0)*Mtot + m0 + mcol]; \
        ra1 = W[(size_t)((c)*8 + tt0 + 4)*Mtot + m0 + mcol]; \
        if (bsplit) { \
            rb0 = Bsp[(size_t)((c)*8 + tt0)*HW + n0 + mcol]; \
            rb1 = Bsp[(size_t)((c)*8 + tt0 + 4)*HW + n0 + mcol]; \
        } else { \
            const float* xp0 = &Bf[(size_t)((c)*16 + 2*tt0)*HW + n0 + mcol]; \
            f00 = xp0[0]; f01 = xp0[HW]; \
            const float* xp1 = &Bf[(size_t)((c)*16 + 2*tt0 + 8)*HW + n0 + mcol]; \
            f10 = xp1[0]; f11 = xp1[HW]; \
        } \
    } while(0)

#define G_STORE(s) do { \
        As[s][0][tt0][mcol] = ra0.x;   As[s][1][tt0][mcol] = ra0.y; \
        As[s][0][tt0+4][mcol] = ra1.x; As[s][1][tt0+4][mcol] = ra1.y; \
        if (bsplit) { \
            Bs[s][0][tt0][mcol] = rb0.x;   Bs[s][1][tt0][mcol] = rb0.y; \
            Bs[s][0][tt0+4][mcol] = rb1.x; Bs[s][1][tt0+4][mcol] = rb1.y; \
        } else { \
            uint32_t hi_, lo_; \
            split2(f00, f01, hi_, lo_); \
            Bs[s][0][tt0][mcol] = hi_;   Bs[s][1][tt0][mcol] = lo_; \
            split2(f10, f11, hi_, lo_); \
            Bs[s][0][tt0+4][mcol] = hi_; Bs[s][1][tt0+4][mcol] = lo_; \
        } \
    } while(0)

    G_LOAD(0); G_STORE(0);
    __syncthreads();
    for (int c = 0; c < nk; c++) {
        const int cur = c & 1;
        if (c + 1 < nk) G_LOAD(c + 1);

        const int mrow = wm*16 + g;
        uint32_t ah0 = As[cur][0][t  ][mrow], ah1 = As[cur][0][t  ][mrow+8];
        uint32_t ah2 = As[cur][0][t+4][mrow], ah3 = As[cur][0][t+4][mrow+8];
        uint32_t al0 = As[cur][1][t  ][mrow], al1 = As[cur][1][t  ][mrow+8];
        uint32_t al2 = As[cur][1][t+4][mrow], al3 = As[cur][1][t+4][mrow+8];
        #pragma unroll
        for (int nt = 0; nt < 4; nt++) {
            int col = wn*32 + nt*8 + g;
            uint32_t bh0 = Bs[cur][0][t][col], bh1 = Bs[cur][0][t+4][col];
            uint32_t bl0 = Bs[cur][1][t][col], bl1 = Bs[cur][1][t+4][col];
            mma_bf16(acc[nt], ah0, ah1, ah2, ah3, bh0, bh1);
            mma_bf16(acc[nt], ah0, ah1, ah2, ah3, bl0, bl1);
            mma_bf16(acc[nt], al0, al1, al2, al3, bh0, bh1);
        }
        if (c + 1 < nk) G_STORE(cur ^ 1);
        __syncthreads();
    }
#undef G_LOAD
#undef G_STORE

    const int row0 = m0 + wm*16 + g;
    const float b0v = bias ? bias[row0]     : 0.f;
    const float b1v = bias ? bias[row0 + 8] : 0.f;
    const float* Rb = res ? res + (size_t)b*Mtot*HW : nullptr;

    #pragma unroll
    for (int nt = 0; nt < 4; nt++) {
        int col = n0 + wn*32 + nt*8 + 2*t;
        float v00 = acc[nt][0] + b0v, v01 = acc[nt][1] + b0v;
        float v10 = acc[nt][2] + b1v, v11 = acc[nt][3] + b1v;
        if (Rb) {
            float2 r0 = *(const float2*)&Rb[(size_t)row0*HW + col];
            float2 r1 = *(const float2*)&Rb[(size_t)(row0+8)*HW + col];
            v00 += r0.x; v01 += r0.y; v10 += r1.x; v11 += r1.y;
        }
        if (!osplit) {
            float* Yb = (float*)Out + (size_t)b*Mtot*HW;
            *(float2*)&Yb[(size_t)row0*HW + col]     = make_float2(v00, v01);
            *(float2*)&Yb[(size_t)(row0+8)*HW + col] = make_float2(v10, v11);
        } else {
            float p00 = __shfl_xor_sync(0xffffffffu, v00, 4);
            float p01 = __shfl_xor_sync(0xffffffffu, v01, 4);
            float p10 = __shfl_xor_sync(0xffffffffu, v10, 4);
            float p11 = __shfl_xor_sync(0xffffffffu, v11, 4);
            if (!(g & 1)) {
                uint2* Osp = (uint2*)Out + (size_t)b*(Mtot/2)*HW;
                int c2 = row0 >> 1;
                uint32_t h0,l0,h1,l1;
                split2(v00, p00, h0, l0); split2(v01, p01, h1, l1);
                *(uint4*)&Osp[(size_t)c2*HW + col] = make_uint4(h0,l0,h1,l1);
                split2(v10, p10, h0, l0); split2(v11, p11, h1, l1);
                *(uint4*)&Osp[(size_t)(c2+4)*HW + col] = make_uint4(h0,l0,h1,l1);
            }
        }
    }
}

// ---------------- dilated 3x3 conv (bf16x3, pipelined, split-B in, fp32 out + bn partials) ----
__global__ void conv3x3_bf3(const uint2* __restrict__ Bsp, const uint2* __restrict__ CW,
                            const float* __restrict__ bias, float* __restrict__ Y, int d)
{
    const int m0 = blockIdx.x * 64;
    const int y  = blockIdx.y;
    const int b  = blockIdx.z;
    const uint2* Xb = Bsp + (size_t)b*64*HW;

    __shared__ uint32_t As[2][2][8][72];
    __shared__ uint32_t Bs[2][2][8][104];
    __shared__ float sS[2][64], sQ[2][64];

    const int tid  = threadIdx.x;
    const int warp = tid >> 5, lane = tid & 31;
    const int wm = warp >> 1, wn = warp & 1;
    const int g = lane >> 2, t = lane & 3;
    const int tt0 = tid >> 6, mcol = tid & 63;

    // valid tap list
    int tidx[9], txs[9];
    const uint2* trow[9];
    int nv = 0;
    #pragma unroll
    for (int tap = 0; tap < 9; tap++) {
        int dy = tap/3 - 1, dx = tap%3 - 1;
        int yy = y + dy*d;
        if (yy >= 0 && yy < HH) {
            tidx[nv] = tap; txs[nv] = dx*d;
            trow[nv] = Xb + (size_t)yy*WW;
            nv++;
        }
    }
    const int nchunks = nv * 8;

    float acc[6][4] = {};
    uint2 ra0, ra1, rb[3];

#define C_LOAD(cc) do { \
        int tv_ = (cc) >> 3, icb_ = ((cc) & 7) * 8; \
        const uint2* Wt_ = CW + (size_t)tidx[tv_]*64*DIM; \
        ra0 = Wt_[(size_t)(icb_ + tt0)*DIM + m0 + mcol]; \
        ra1 = Wt_[(size_t)(icb_ + tt0 + 4)*DIM + m0 + mcol]; \
        const uint2* Xr_ = trow[tv_]; int xs_ = txs[tv_]; \
        _Pragma("unroll") \
        for (int j_ = 0; j_ < 3; j_++) { \
            int i_ = tid + j_*256; int tt_ = i_ / 96; int n_ = i_ - 96*tt_; \
            int xx_ = n_ + xs_; \
            rb[j_] = (xx_ >= 0 && xx_ < WW) ? Xr_[(size_t)(icb_ + tt_)*HW + xx_] \
                                            : make_uint2(0u, 0u); \
        } \
    } while(0)

#define C_STORE(s) do { \
        As[s][0][tt0][mcol] = ra0.x;   As[s][1][tt0][mcol] = ra0.y; \
        As[s][0][tt0+4][mcol] = ra1.x; As[s][1][tt0+4][mcol] = ra1.y; \
        _Pragma("unroll") \
        for (int j_ = 0; j_ < 3; j_++) { \
            int i_ = tid + j_*256; int tt_ = i_ / 96; int n_ = i_ - 96*tt_; \
            Bs[s][0][tt_][n_] = rb[j_].x; Bs[s][1][tt_][n_] = rb[j_].y; \
        } \
    } while(0)

    C_LOAD(0); C_STORE(0);
    __syncthreads();
    for (int cc = 0; cc < nchunks; cc++) {
        const int cur = cc & 1;
        if (cc + 1 < nchunks) C_LOAD(cc + 1);

        const int mrow = wm*16 + g;
        uint32_t ah0 = As[cur][0][t  ][mrow], ah1 = As[cur][0][t  ][mrow+8];
        uint32_t ah2 = As[cur][0][t+4][mrow], ah3 = As[cur][0][t+4][mrow+8];
        uint32_t al0 = As[cur][1][t  ][mrow], al1 = As[cur][1][t  ][mrow+8];
        uint32_t al2 = As[cur][1][t+4][mrow], al3 = As[cur][1][t+4][mrow+8];
        #pragma unroll
        for (int nt = 0; nt < 6; nt++) {
            int col = wn*48 + nt*8 + g;
            uint32_t bh0 = Bs[cur][0][t][col], bh1 = Bs[cur][0][t+4][col];
            uint32_t bl0 = Bs[cur][1][t][col], bl1 = Bs[cur][1][t+4][col];
            mma_bf16(acc[nt], ah0, ah1, ah2, ah3, bh0, bh1);
            mma_bf16(acc[nt], ah0, ah1, ah2, ah3, bl0, bl1);
            mma_bf16(acc[nt], al0, al1, al2, al3, bh0, bh1);
        }
        if (cc + 1 < nchunks) C_STORE(cur ^ 1);
        __syncthreads();
    }
#undef C_LOAD
#undef C_STORE

    float* Yb = Y + (size_t)b*DIM*HW + (size_t)y*WW;
    const int row0 = m0 + wm*16 + g;
    const float b0v = bias[row0], b1v = bias[row0 + 8];
    float s0 = 0.f, q0 = 0.f, s1 = 0.f, q1 = 0.f;
    #pragma unroll
    for (int nt = 0; nt < 6; nt++) {
        int col = wn*48 + nt*8 + 2*t;
        float v00 = acc[nt][0] + b0v, v01 = acc[nt][1] + b0v;
        float v10 = acc[nt][2] + b1v, v11 = acc[nt][3] + b1v;
        *(float2*)&Yb[(size_t)row0*HW + col]     = make_float2(v00, v01);
        *(float2*)&Yb[(size_t)(row0+8)*HW + col] = make_float2(v10, v11);
        s0 += v00 + v01; q0 += v00*v00 + v01*v01;
        s1 += v10 + v11; q1 += v10*v10 + v11*v11;
    }
    #pragma unroll
    for (int o = 1; o <= 2; o <<= 1) {
        s0 += __shfl_xor_sync(0xffffffffu, s0, o);
        q0 += __shfl_xor_sync(0xffffffffu, q0, o);
        s1 += __shfl_xor_sync(0xffffffffu, s1, o);
        q1 += __shfl_xor_sync(0xffffffffu, q1, o);
    }
    if (t == 0) {
        int lr = wm*16 + g;
        sS[wn][lr] = s0; sQ[wn][lr] = q0;
        sS[wn][lr+8] = s1; sQ[wn][lr+8] = q1;
    }
    __syncthreads();
    if (tid < 64) {
        int idx = b*HH + y;
        g_ps[(size_t)(m0+tid)*NIDX + idx] = sS[0][tid] + sS[1][tid];
        g_pq[(size_t)(m0+tid)*NIDX + idx] = sQ[0][tid] + sQ[1][tid];
    }
}

// ---------------- bn finalize (parallel: DIM blocks x 192 threads) ----------------
__global__ void bn_finalize()
{
    const int c = blockIdx.x;
    float s = g_ps[(size_t)c*NIDX + threadIdx.x];
    float q = g_pq[(size_t)c*NIDX + threadIdx.x];
    #pragma unroll
    for (int o = 16; o > 0; o >>= 1) {
        s += __shfl_xor_sync(0xffffffffu, s, o);
        q += __shfl_xor_sync(0xffffffffu, q, o);
    }
    __shared__ float ss[6], sq[6];
    int w = threadIdx.x >> 5;
    if ((threadIdx.x & 31) == 0) { ss[w] = s; sq[w] = q; }
    __syncthreads();
    if (threadIdx.x == 0) {
        s = 0.f; q = 0.f;
        #pragma unroll
        for (int i = 0; i < 6; i++) { s += ss[i]; q += sq[i]; }
        const float invN = 1.f / (BATCH*HW);
        float m = s * invN;
        float var = q * invN - m*m;
        g_mean[c] = m;
        g_rstd[c] = rsqrtf(var + 1e-5f);
    }
}

// ---------------- bn apply + relu: writes fp32 residual + split qkv-input ----------------
__global__ void bn_apply_relu(const float* __restrict__ X, const float* __restrict__ gam,
                              const float* __restrict__ beta, float* __restrict__ Yf,
                              uint2* __restrict__ Ysp)
{
    const int b = blockIdx.y;
    int i = blockIdx.x*256 + threadIdx.x;
    int c2 = i / (HW/4);
    int p  = (i - c2*(HW/4)) * 4;
    const float* Xb = X + (size_t)b*DIM*HW;
    float* Yb = Yf + (size_t)b*DIM*HW;
    uint2* Sb = Ysp + (size_t)b*64*HW;

    int c0 = 2*c2, c1 = 2*c2 + 1;
    float m0 = g_mean[c0], r0 = g_rstd[c0], ga0 = gam[c0], be0 = beta[c0];
    float m1 = g_mean[c1], r1 = g_rstd[c1], ga1 = gam[c1], be1 = beta[c1];

    float4 a = *(const float4*)&Xb[(size_t)c0*HW + p];
    float4 c = *(const float4*)&Xb[(size_t)c1*HW + p];
    float y0x = fmaxf((a.x-m0)*r0*ga0+be0, 0.f), y0y = fmaxf((a.y-m0)*r0*ga0+be0, 0.f);
    float y0z = fmaxf((a.z-m0)*r0*ga0+be0, 0.f), y0w = fmaxf((a.w-m0)*r0*ga0+be0, 0.f);
    float y1x = fmaxf((c.x-m1)*r1*ga1+be1, 0.f), y1y = fmaxf((c.y-m1)*r1*ga1+be1, 0.f);
    float y1z = fmaxf((c.z-m1)*r1*ga1+be1, 0.f), y1w = fmaxf((c.w-m1)*r1*ga1+be1, 0.f);

    *(float4*)&Yb[(size_t)c0*HW + p] = make_float4(y0x, y0y, y0z, y0w);
    *(float4*)&Yb[(size_t)c1*HW + p] = make_float4(y1x, y1y, y1z, y1w);

    uint32_t h0,l0,h1,l1,h2,l2,h3,l3;
    split2(y0x, y1x, h0, l0); split2(y0y, y1y, h1, l1);
    split2(y0z, y1z, h2, l2); split2(y0w, y1w, h3, l3);
    uint4* dst = (uint4*)&Sb[(size_t)c2*HW + p];
    dst[0] = make_uint4(h0, l0, h1, l1);
    dst[1] = make_uint4(h2, l2, h3, l3);
}

// ---------------- local channel self-attention (split epilogue) ----------------
__global__ void attn_core(const float* __restrict__ QKV, uint2* __restrict__ OUT)
{
    const int b = blockIdx.z, h = blockIdx.y;
    const int p0 = blockIdx.x * 32;
    const int y  = p0 / WW, x0 = p0 % WW;
    const float* Qb = QKV + ((size_t)b*3*DIM + h*CH)*HW;
    const float* Kb = Qb + (size_t)DIM*HW;
    const float* Vb = Qb + (size_t)2*DIM*HW;

    __shared__ float qs[CH][3][34];
    __shared__ float ks[CH][3][34];
    __shared__ float vs[CH][3][34];
    __shared__ float sato[CH][33];

    const int tid = threadIdx.y*32 + threadIdx.x;
    for (int i = tid; i < CH*3*34; i += 512) {
        int xi = i % 34; int rr = i / 34; int yi = rr % 3; int c = rr / 3;
        int yy = y + yi - 1, xx = x0 + xi - 1;
        bool ok = (yy >= 0 && yy < HH && xx >= 0 && xx < WW);
        int o = c*HW + yy*WW + xx;
        qs[c][yi][xi] = ok ? Qb[o] : 0.f;
        ks[c][yi][xi] = ok ? Kb[o] : 0.f;
        vs[c][yi][xi] = ok ? Vb[o] : 0.f;
    }
    __syncthreads();

    const int n = threadIdx.y, lx = threadIdx.x;
    float qr[9];
    #pragma unroll
    for (int t = 0; t < 9; t++) qr[t] = qs[n][t/3][lx + t%3] * 0.25f;

    float dots[CH], vsum[CH];
    #pragma unroll
    for (int m = 0; m < CH; m++) {
        float dv = 0.f, sv = 0.f;
        #pragma unroll
        for (int t = 0; t < 9; t++) {
            dv += qr[t] * ks[m][t/3][lx + t%3];
            sv += vs[m][t/3][lx + t%3];
        }
        dots[m] = dv; vsum[m] = sv;
    }
    float mx = dots[0];
    #pragma unroll
    for (int m = 1; m < CH; m++) mx = fmaxf(mx, dots[m]);
    float s = 0.f;
    #pragma unroll
    for (int m = 0; m < CH; m++) { dots[m] = __expf(dots[m]-mx); s += dots[m]; }
    float o = 0.f;
    #pragma unroll
    for (int m = 0; m < CH; m++) o += dots[m]*vsum[m];
    sato[n][lx] = o / s;
    __syncthreads();

    if (n < 8) {
        float v0 = sato[2*n][lx], v1 = sato[2*n+1][lx];
        uint32_t hi, lo; split2(v0, v1, hi, lo);
        OUT[(size_t)b*64*HW + (size_t)(h*8 + n)*HW + p0 + lx] = make_uint2(hi, lo);
    }
}

// ---------------- host orchestration ----------------
extern "C" void kernel_launch(void* const* d_in, const int* in_sizes, int n_in,
                              void* d_out, int out_size)
{
    const float* x      = (const float*)d_in[0];
    const float* w_in   = (const float*)d_in[1];
    const float* b_in   = (const float*)d_in[2];
    const float* conv_w = (const float*)d_in[3];
    const float* conv_b = (const float*)d_in[4];
    const float* bn_g   = (const float*)d_in[5];
    const float* bn_b   = (const float*)d_in[6];
    const float* qkv_w  = (const float*)d_in[7];
    const float* fc_w   = (const float*)d_in[8];
    const float* fc_b   = (const float*)d_in[9];
    const float* w_out  = (const float*)d_in[10];
    const float* b_out  = (const float*)d_in[11];
    float* out = (float*)d_out;

    float *p_t, *p_bn, *p_qkv;
    uint2 *p_hsp, *p_qsp, *p_asp, *p_cw, *p_qw, *p_fw, *p_wi, *p_wo;
    cudaGetSymbolAddress((void**)&p_t,    g_t);
    cudaGetSymbolAddress((void**)&p_bn,   g_bn);
    cudaGetSymbolAddress((void**)&p_qkv,  g_qkv);
    cudaGetSymbolAddress((void**)&p_hsp,  g_hsp);
    cudaGetSymbolAddress((void**)&p_qsp,  g_qsp);
    cudaGetSymbolAddress((void**)&p_asp,  g_asp);
    cudaGetSymbolAddress((void**)&p_cw,   g_cw);
    cudaGetSymbolAddress((void**)&p_qw,   g_qw);
    cudaGetSymbolAddress((void**)&p_fw,   g_fw);
    cudaGetSymbolAddress((void**)&p_wi,   g_wi);
    cudaGetSymbolAddress((void**)&p_wo,   g_wo);

    prep_all<<<(NC+NQ+NF+NI+NO + 255)/256, 256>>>(conv_w, qkv_w, fc_w, w_in, w_out);

    // input projection 64 -> 128, split output into g_hsp
    {
        dim3 g(HW/64, DIM/64, BATCH);
        gemm_bf3<<<g, 256>>>(p_wi, x, 0, b_in, nullptr, p_hsp, 1, DIM, CIN);
    }

    for (int i = 0; i < DEPTH; i++) {
        const int d = 1 << i;
        {
            dim3 g(2, HH, BATCH);
            conv3x3_bf3<<<g, 256>>>(p_hsp, p_cw + (size_t)i*9*64*DIM,
                                    conv_b + i*DIM, p_t, d);
        }
        bn_finalize<<<DIM, 192>>>();
        {
            dim3 g((64*HW/4)/256, BATCH);
            bn_apply_relu<<<g, 256>>>(p_t, bn_g + i*DIM, bn_b + i*DIM, p_bn, p_qsp);
        }
        {
            dim3 g(HW/64, (3*DIM)/64, BATCH);
            gemm_bf3<<<g, 256>>>(p_qw + (size_t)i*64*3*DIM, p_qsp, 1, nullptr, nullptr,
                                 p_qkv, 0, 3*DIM, DIM);
        }
        {
            dim3 g(HW/32, HEADS, BATCH);
            dim3 blk(32, CH);
            attn_core<<<g, blk>>>(p_qkv, p_asp);
        }
        {
            dim3 g(HW/64, DIM/64, BATCH);
            gemm_bf3<<<g, 256>>>(p_fw + (size_t)i*64*DIM, p_asp, 1, fc_b + i*DIM, p_bn,
                                 p_hsp, 1, DIM, DIM);
        }
    }

    {
        dim3 g(HW/64, COUT/64, BATCH);
        gemm_bf3<<<g, 256>>>(p_wo, p_hsp, 1, b_out, nullptr, out, 0, COUT, DIM);
    }
}

// round 6
// speedup vs baseline: 1.3823x; 1.0250x over previous
#include <cuda_runtime.h>
#include <cuda_bf16.h>
#include <cstdint>
#include <cstddef>

#define BATCH 2
#define DIM 128
#define CIN 64
#define COUT 64
#define HH 96
#define WW 96
#define HW (HH*WW)           // 9216
#define HEADS 8
#define CH 16
#define DEPTH 4
#define NIDX (BATCH*HH)      // 192 (b,y) slots for bn partials

// ---------------- scratch (device globals) ----------------
__device__ __align__(16) float g_t  [BATCH*DIM*HW];   // conv out (fp32, pre-BN)
__device__ __align__(16) float g_bn [BATCH*DIM*HW];   // bn+relu out (fp32 residual)
__device__ __align__(16) float g_qkv[BATCH*3*DIM*HW];
__device__ __align__(16) uint2 g_hsp[BATCH*64*HW];    // split h   (conv / out-proj B)
__device__ __align__(16) uint2 g_qsp[BATCH*64*HW];    // split bn  (qkv B)
__device__ __align__(16) uint2 g_asp[BATCH*64*HW];    // split att (fc B)
__device__ float g_ps[DIM*NIDX];                      // bn partial sums
__device__ float g_pq[DIM*NIDX];                      // bn partial sumsq
// packed split weights: uint2 {hi,lo}, layout [K/2][M]
__device__ uint2 g_cw[DEPTH*9*64*DIM];   // [d][tap][ic2][oc]
__device__ uint2 g_qw[DEPTH*64*3*DIM];
__device__ uint2 g_fw[DEPTH*64*DIM];
__device__ uint2 g_wi[32*DIM];
__device__ uint2 g_wo[64*COUT];

__device__ __forceinline__ void split2(float x0, float x1, uint32_t& hi, uint32_t& lo)
{
    __nv_bfloat16 h0 = __float2bfloat16(x0);
    __nv_bfloat16 h1 = __float2bfloat16(x1);
    float l0f = x0 - __bfloat162float(h0);
    float l1f = x1 - __bfloat162float(h1);
    __nv_bfloat162 hh = __halves2bfloat162(h0, h1);
    __nv_bfloat162 ll = __halves2bfloat162(__float2bfloat16(l0f), __float2bfloat16(l1f));
    hi = *reinterpret_cast<uint32_t*>(&hh);
    lo = *reinterpret_cast<uint32_t*>(&ll);
}

__device__ __forceinline__ void mma_bf16(float c[4],
    uint32_t a0, uint32_t a1, uint32_t a2, uint32_t a3, uint32_t b0, uint32_t b1)
{
    asm volatile(
        "mma.sync.aligned.m16n8k16.row.col.f32.bf16.bf16.f32 "
        "{%0,%1,%2,%3}, {%4,%5,%6,%7}, {%8,%9}, {%0,%1,%2,%3};"
        : "+f"(c[0]), "+f"(c[1]), "+f"(c[2]), "+f"(c[3])
        : "r"(a0), "r"(a1), "r"(a2), "r"(a3), "r"(b0), "r"(b1));
}

// ---------------- unified weight prep (single launch) ----------------
#define NC (DEPTH*9*64*DIM)
#define NQ (DEPTH*64*3*DIM)
#define NF (DEPTH*64*DIM)
#define NI (32*DIM)
#define NO (64*COUT)
__global__ void prep_all(const float* __restrict__ conv_w, const float* __restrict__ qkv_w,
                         const float* __restrict__ fc_w, const float* __restrict__ w_in,
                         const float* __restrict__ w_out)
{
    int i = blockIdx.x*256 + threadIdx.x;
    float x0, x1; uint2* dst;
    if (i < NC) {
        int oc = i & 127; int r = i >> 7; int ic2 = r & 63; r >>= 6;
        int tap = r % 9, d = r / 9;
        size_t base = ((size_t)(d*DIM + oc)*DIM + 2*ic2)*9 + tap;
        x0 = conv_w[base]; x1 = conv_w[base + 9]; dst = &g_cw[i];
    } else if (i < NC+NQ) {
        int j = i - NC; int d = j / (64*384); int l = j % (64*384);
        int k2 = l / 384, m = l % 384;
        x0 = qkv_w[((size_t)d*384 + m)*DIM + 2*k2];
        x1 = qkv_w[((size_t)d*384 + m)*DIM + 2*k2 + 1];
        dst = &g_qw[j];
    } else if (i < NC+NQ+NF) {
        int j = i - NC - NQ; int d = j / (64*DIM); int l = j % (64*DIM);
        int k2 = l / DIM, m = l % DIM;
        x0 = fc_w[((size_t)d*DIM + m)*DIM + 2*k2];
        x1 = fc_w[((size_t)d*DIM + m)*DIM + 2*k2 + 1];
        dst = &g_fw[j];
    } else if (i < NC+NQ+NF+NI) {
        int j = i - NC - NQ - NF; int k2 = j / DIM, m = j % DIM;
        x0 = w_in[(size_t)m*CIN + 2*k2]; x1 = w_in[(size_t)m*CIN + 2*k2 + 1];
        dst = &g_wi[j];
    } else if (i < NC+NQ+NF+NI+NO) {
        int j = i - NC - NQ - NF - NI; int k2 = j / COUT, m = j % COUT;
        x0 = w_out[(size_t)m*DIM + 2*k2]; x1 = w_out[(size_t)m*DIM + 2*k2 + 1];
        dst = &g_wo[j];
    } else return;
    uint32_t hi, lo; split2(x0, x1, hi, lo);
    *dst = make_uint2(hi, lo);
}

// ---------------- unified bf16x3 GEMM (2-stage pipelined, 64m x 128n block) ----------------
// W: [K/2][Mtot] uint2. B: pre-split uint2 [K/2][HW] (bsplit=1) or fp32 [K][HW].
// Out: fp32 [Mtot][HW] (osplit=0) or split uint2 [Mtot/2][HW] (osplit=1).
// 256 thr = 8 warps (2m x 4n); warp tile 32m x 32n.
__global__ void gemm_bf3(const uint2* __restrict__ W, const void* __restrict__ Bin, int bsplit,
                         const float* __restrict__ bias, const float* __restrict__ res,
                         void* __restrict__ Out, int osplit, int Mtot, int K)
{
    const int b  = blockIdx.z;
    const int m0 = blockIdx.y * 64, n0 = blockIdx.x * 128;

    __shared__ uint32_t As[2][2][8][72];
    __shared__ uint32_t Bs[2][2][8][136];

    const int tid  = threadIdx.x;
    const int warp = tid >> 5, lane = tid & 31;
    const int wm = warp >> 2, wn = warp & 3;
    const int g = lane >> 2, t = lane & 3;
    const int tt0 = tid >> 6, mcol = tid & 63;

    const uint2* Bsp = (const uint2*)Bin + (size_t)b*(K/2)*HW;
    const float* Bf  = (const float*)Bin + (size_t)b*K*HW;

    const int nk = K/16;
    float acc[2][4][4] = {};

    uint2 ra0, ra1, rb[4];
    float f0[4], f1[4];

#define G_LOAD(c) do { \
        ra0 = W[(size_t)((c)*8 + tt0)*Mtot + m0 + mcol]; \
        ra1 = W[(size_t)((c)*8 + tt0 + 4)*Mtot + m0 + mcol]; \
        if (bsplit) { \
            _Pragma("unroll") \
            for (int j_ = 0; j_ < 4; j_++) { \
                int i_ = tid + j_*256; int tt_ = i_ >> 7; int n_ = i_ & 127; \
                rb[j_] = Bsp[(size_t)((c)*8 + tt_)*HW + n0 + n_]; \
            } \
        } else { \
            _Pragma("unroll") \
            for (int j_ = 0; j_ < 4; j_++) { \
                int i_ = tid + j_*256; int tt_ = i_ >> 7; int n_ = i_ & 127; \
                const float* xp_ = &Bf[(size_t)((c)*16 + 2*tt_)*HW + n0 + n_]; \
                f0[j_] = xp_[0]; f1[j_] = xp_[HW]; \
            } \
        } \
    } while(0)

#define G_STORE(s) do { \
        As[s][0][tt0][mcol] = ra0.x;   As[s][1][tt0][mcol] = ra0.y; \
        As[s][0][tt0+4][mcol] = ra1.x; As[s][1][tt0+4][mcol] = ra1.y; \
        _Pragma("unroll") \
        for (int j_ = 0; j_ < 4; j_++) { \
            int i_ = tid + j_*256; int tt_ = i_ >> 7; int n_ = i_ & 127; \
            if (bsplit) { \
                Bs[s][0][tt_][n_] = rb[j_].x; Bs[s][1][tt_][n_] = rb[j_].y; \
            } else { \
                uint32_t hi_, lo_; split2(f0[j_], f1[j_], hi_, lo_); \
                Bs[s][0][tt_][n_] = hi_; Bs[s][1][tt_][n_] = lo_; \
            } \
        } \
    } while(0)

    G_LOAD(0); G_STORE(0);
    __syncthreads();
    for (int c = 0; c < nk; c++) {
        const int cur = c & 1;
        if (c + 1 < nk) G_LOAD(c + 1);

        uint32_t ah[2][4], al[2][4];
        #pragma unroll
        for (int mt = 0; mt < 2; mt++) {
            int mrow = wm*32 + mt*16 + g;
            ah[mt][0] = As[cur][0][t  ][mrow]; ah[mt][1] = As[cur][0][t  ][mrow+8];
            ah[mt][2] = As[cur][0][t+4][mrow]; ah[mt][3] = As[cur][0][t+4][mrow+8];
            al[mt][0] = As[cur][1][t  ][mrow]; al[mt][1] = As[cur][1][t  ][mrow+8];
            al[mt][2] = As[cur][1][t+4][mrow]; al[mt][3] = As[cur][1][t+4][mrow+8];
        }
        #pragma unroll
        for (int nt = 0; nt < 4; nt++) {
            int col = wn*32 + nt*8 + g;
            uint32_t bh0 = Bs[cur][0][t][col], bh1 = Bs[cur][0][t+4][col];
            uint32_t bl0 = Bs[cur][1][t][col], bl1 = Bs[cur][1][t+4][col];
            #pragma unroll
            for (int mt = 0; mt < 2; mt++) {
                mma_bf16(acc[mt][nt], ah[mt][0], ah[mt][1], ah[mt][2], ah[mt][3], bh0, bh1);
                mma_bf16(acc[mt][nt], ah[mt][0], ah[mt][1], ah[mt][2], ah[mt][3], bl0, bl1);
                mma_bf16(acc[mt][nt], al[mt][0], al[mt][1], al[mt][2], al[mt][3], bh0, bh1);
            }
        }
        if (c + 1 < nk) G_STORE(cur ^ 1);
        __syncthreads();
    }
#undef G_LOAD
#undef G_STORE

    const float* Rb = res ? res + (size_t)b*Mtot*HW : nullptr;

    #pragma unroll
    for (int mt = 0; mt < 2; mt++) {
        const int row0 = m0 + wm*32 + mt*16 + g;
        const float b0v = bias ? bias[row0]     : 0.f;
        const float b1v = bias ? bias[row0 + 8] : 0.f;
        #pragma unroll
        for (int nt = 0; nt < 4; nt++) {
            int col = n0 + wn*32 + nt*8 + 2*t;
            float v00 = acc[mt][nt][0] + b0v, v01 = acc[mt][nt][1] + b0v;
            float v10 = acc[mt][nt][2] + b1v, v11 = acc[mt][nt][3] + b1v;
            if (Rb) {
                float2 r0 = *(const float2*)&Rb[(size_t)row0*HW + col];
                float2 r1 = *(const float2*)&Rb[(size_t)(row0+8)*HW + col];
                v00 += r0.x; v01 += r0.y; v10 += r1.x; v11 += r1.y;
            }
            if (!osplit) {
                float* Yb = (float*)Out + (size_t)b*Mtot*HW;
                *(float2*)&Yb[(size_t)row0*HW + col]     = make_float2(v00, v01);
                *(float2*)&Yb[(size_t)(row0+8)*HW + col] = make_float2(v10, v11);
            } else {
                float p00 = __shfl_xor_sync(0xffffffffu, v00, 4);
                float p01 = __shfl_xor_sync(0xffffffffu, v01, 4);
                float p10 = __shfl_xor_sync(0xffffffffu, v10, 4);
                float p11 = __shfl_xor_sync(0xffffffffu, v11, 4);
                if (!(g & 1)) {
                    uint2* Osp = (uint2*)Out + (size_t)b*(Mtot/2)*HW;
                    int c2 = row0 >> 1;
                    uint32_t h0,l0,h1,l1;
                    split2(v00, p00, h0, l0); split2(v01, p01, h1, l1);
                    *(uint4*)&Osp[(size_t)c2*HW + col] = make_uint4(h0,l0,h1,l1);
                    split2(v10, p10, h0, l0); split2(v11, p11, h1, l1);
                    *(uint4*)&Osp[(size_t)(c2+4)*HW + col] = make_uint4(h0,l0,h1,l1);
                }
            }
        }
    }
}

// ---------------- dilated 3x3 conv (bf16x3, pipelined, split-B in, fp32 out + bn partials) ----
__global__ void conv3x3_bf3(const uint2* __restrict__ Bsp, const uint2* __restrict__ CW,
                            const float* __restrict__ bias, float* __restrict__ Y, int d)
{
    const int m0 = blockIdx.x * 64;
    const int y  = blockIdx.y;
    const int b  = blockIdx.z;
    const uint2* Xb = Bsp + (size_t)b*64*HW;

    __shared__ uint32_t As[2][2][8][72];
    __shared__ uint32_t Bs[2][2][8][104];
    __shared__ float sS[2][64], sQ[2][64];

    const int tid  = threadIdx.x;
    const int warp = tid >> 5, lane = tid & 31;
    const int wm = warp >> 1, wn = warp & 1;
    const int g = lane >> 2, t = lane & 3;
    const int tt0 = tid >> 6, mcol = tid & 63;

    int tidx[9], txs[9];
    const uint2* trow[9];
    int nv = 0;
    #pragma unroll
    for (int tap = 0; tap < 9; tap++) {
        int dy = tap/3 - 1, dx = tap%3 - 1;
        int yy = y + dy*d;
        if (yy >= 0 && yy < HH) {
            tidx[nv] = tap; txs[nv] = dx*d;
            trow[nv] = Xb + (size_t)yy*WW;
            nv++;
        }
    }
    const int nchunks = nv * 8;

    float acc[6][4] = {};
    uint2 ra0, ra1, rb[3];

#define C_LOAD(cc) do { \
        int tv_ = (cc) >> 3, icb_ = ((cc) & 7) * 8; \
        const uint2* Wt_ = CW + (size_t)tidx[tv_]*64*DIM; \
        ra0 = Wt_[(size_t)(icb_ + tt0)*DIM + m0 + mcol]; \
        ra1 = Wt_[(size_t)(icb_ + tt0 + 4)*DIM + m0 + mcol]; \
        const uint2* Xr_ = trow[tv_]; int xs_ = txs[tv_]; \
        _Pragma("unroll") \
        for (int j_ = 0; j_ < 3; j_++) { \
            int i_ = tid + j_*256; int tt_ = i_ / 96; int n_ = i_ - 96*tt_; \
            int xx_ = n_ + xs_; \
            rb[j_] = (xx_ >= 0 && xx_ < WW) ? Xr_[(size_t)(icb_ + tt_)*HW + xx_] \
                                            : make_uint2(0u, 0u); \
        } \
    } while(0)

#define C_STORE(s) do { \
        As[s][0][tt0][mcol] = ra0.x;   As[s][1][tt0][mcol] = ra0.y; \
        As[s][0][tt0+4][mcol] = ra1.x; As[s][1][tt0+4][mcol] = ra1.y; \
        _Pragma("unroll") \
        for (int j_ = 0; j_ < 3; j_++) { \
            int i_ = tid + j_*256; int tt_ = i_ / 96; int n_ = i_ - 96*tt_; \
            Bs[s][0][tt_][n_] = rb[j_].x; Bs[s][1][tt_][n_] = rb[j_].y; \
        } \
    } while(0)

    C_LOAD(0); C_STORE(0);
    __syncthreads();
    for (int cc = 0; cc < nchunks; cc++) {
        const int cur = cc & 1;
        if (cc + 1 < nchunks) C_LOAD(cc + 1);

        const int mrow = wm*16 + g;
        uint32_t ah0 = As[cur][0][t  ][mrow], ah1 = As[cur][0][t  ][mrow+8];
        uint32_t ah2 = As[cur][0][t+4][mrow], ah3 = As[cur][0][t+4][mrow+8];
        uint32_t al0 = As[cur][1][t  ][mrow], al1 = As[cur][1][t  ][mrow+8];
        uint32_t al2 = As[cur][1][t+4][mrow], al3 = As[cur][1][t+4][mrow+8];
        #pragma unroll
        for (int nt = 0; nt < 6; nt++) {
            int col = wn*48 + nt*8 + g;
            uint32_t bh0 = Bs[cur][0][t][col], bh1 = Bs[cur][0][t+4][col];
            uint32_t bl0 = Bs[cur][1][t][col], bl1 = Bs[cur][1][t+4][col];
            mma_bf16(acc[nt], ah0, ah1, ah2, ah3, bh0, bh1);
            mma_bf16(acc[nt], ah0, ah1, ah2, ah3, bl0, bl1);
            mma_bf16(acc[nt], al0, al1, al2, al3, bh0, bh1);
        }
        if (cc + 1 < nchunks) C_STORE(cur ^ 1);
        __syncthreads();
    }
#undef C_LOAD
#undef C_STORE

    float* Yb = Y + (size_t)b*DIM*HW + (size_t)y*WW;
    const int row0 = m0 + wm*16 + g;
    const float b0v = bias[row0], b1v = bias[row0 + 8];
    float s0 = 0.f, q0 = 0.f, s1 = 0.f, q1 = 0.f;
    #pragma unroll
    for (int nt = 0; nt < 6; nt++) {
        int col = wn*48 + nt*8 + 2*t;
        float v00 = acc[nt][0] + b0v, v01 = acc[nt][1] + b0v;
        float v10 = acc[nt][2] + b1v, v11 = acc[nt][3] + b1v;
        *(float2*)&Yb[(size_t)row0*HW + col]     = make_float2(v00, v01);
        *(float2*)&Yb[(size_t)(row0+8)*HW + col] = make_float2(v10, v11);
        s0 += v00 + v01; q0 += v00*v00 + v01*v01;
        s1 += v10 + v11; q1 += v10*v10 + v11*v11;
    }
    #pragma unroll
    for (int o = 1; o <= 2; o <<= 1) {
        s0 += __shfl_xor_sync(0xffffffffu, s0, o);
        q0 += __shfl_xor_sync(0xffffffffu, q0, o);
        s1 += __shfl_xor_sync(0xffffffffu, s1, o);
        q1 += __shfl_xor_sync(0xffffffffu, q1, o);
    }
    if (t == 0) {
        int lr = wm*16 + g;
        sS[wn][lr] = s0; sQ[wn][lr] = q0;
        sS[wn][lr+8] = s1; sQ[wn][lr+8] = q1;
    }
    __syncthreads();
    if (tid < 64) {
        int idx = b*HH + y;
        g_ps[(size_t)(m0+tid)*NIDX + idx] = sS[0][tid] + sS[1][tid];
        g_pq[(size_t)(m0+tid)*NIDX + idx] = sQ[0][tid] + sQ[1][tid];
    }
}

// ---------------- bn apply + relu (inline stats; 2304=9*256 so block has one c2) ----------------
__global__ void bn_apply_relu(const float* __restrict__ X, const float* __restrict__ gam,
                              const float* __restrict__ beta, float* __restrict__ Yf,
                              uint2* __restrict__ Ysp)
{
    const int b = blockIdx.y;
    int i = blockIdx.x*256 + threadIdx.x;
    int c2 = i / (HW/4);
    int p  = (i - c2*(HW/4)) * 4;
    int c0 = 2*c2, c1 = 2*c2 + 1;

    // inline stats reduction for this block's channel pair
    __shared__ float st[4];
    __shared__ float rs[4][8];
    {
        float s0=0.f, q0=0.f, s1=0.f, q1=0.f;
        int tt = threadIdx.x;
        if (tt < NIDX) {
            s0 = g_ps[(size_t)c0*NIDX + tt]; q0 = g_pq[(size_t)c0*NIDX + tt];
            s1 = g_ps[(size_t)c1*NIDX + tt]; q1 = g_pq[(size_t)c1*NIDX + tt];
        }
        #pragma unroll
        for (int o = 16; o > 0; o >>= 1) {
            s0 += __shfl_xor_sync(0xffffffffu, s0, o);
            q0 += __shfl_xor_sync(0xffffffffu, q0, o);
            s1 += __shfl_xor_sync(0xffffffffu, s1, o);
            q1 += __shfl_xor_sync(0xffffffffu, q1, o);
        }
        int w = threadIdx.x >> 5;
        if ((threadIdx.x & 31) == 0) {
            rs[0][w] = s0; rs[1][w] = q0; rs[2][w] = s1; rs[3][w] = q1;
        }
        __syncthreads();
        if (threadIdx.x == 0) {
            float S0=0,Q0=0,S1=0,Q1=0;
            #pragma unroll
            for (int k = 0; k < 8; k++) { S0+=rs[0][k]; Q0+=rs[1][k]; S1+=rs[2][k]; Q1+=rs[3][k]; }
            const float invN = 1.f / (BATCH*HW);
            float mm0 = S0*invN, mm1 = S1*invN;
            st[0] = mm0; st[1] = rsqrtf(Q0*invN - mm0*mm0 + 1e-5f);
            st[2] = mm1; st[3] = rsqrtf(Q1*invN - mm1*mm1 + 1e-5f);
        }
        __syncthreads();
    }
    float m0 = st[0], r0 = st[1], m1 = st[2], r1 = st[3];
    float ga0 = gam[c0], be0 = beta[c0], ga1 = gam[c1], be1 = beta[c1];

    const float* Xb = X + (size_t)b*DIM*HW;
    float* Yb = Yf + (size_t)b*DIM*HW;
    uint2* Sb = Ysp + (size_t)b*64*HW;

    float4 a = *(const float4*)&Xb[(size_t)c0*HW + p];
    float4 c = *(const float4*)&Xb[(size_t)c1*HW + p];
    float y0x = fmaxf((a.x-m0)*r0*ga0+be0, 0.f), y0y = fmaxf((a.y-m0)*r0*ga0+be0, 0.f);
    float y0z = fmaxf((a.z-m0)*r0*ga0+be0, 0.f), y0w = fmaxf((a.w-m0)*r0*ga0+be0, 0.f);
    float y1x = fmaxf((c.x-m1)*r1*ga1+be1, 0.f), y1y = fmaxf((c.y-m1)*r1*ga1+be1, 0.f);
    float y1z = fmaxf((c.z-m1)*r1*ga1+be1, 0.f), y1w = fmaxf((c.w-m1)*r1*ga1+be1, 0.f);

    *(float4*)&Yb[(size_t)c0*HW + p] = make_float4(y0x, y0y, y0z, y0w);
    *(float4*)&Yb[(size_t)c1*HW + p] = make_float4(y1x, y1y, y1z, y1w);

    uint32_t h0,l0,h1,l1,h2,l2,h3,l3;
    split2(y0x, y1x, h0, l0); split2(y0y, y1y, h1, l1);
    split2(y0z, y1z, h2, l2); split2(y0w, y1w, h3, l3);
    uint4* dst = (uint4*)&Sb[(size_t)c2*HW + p];
    dst[0] = make_uint4(h0, l0, h1, l1);
    dst[1] = make_uint4(h2, l2, h3, l3);
}

// ---------------- local channel self-attention (split epilogue) ----------------
__global__ void attn_core(const float* __restrict__ QKV, uint2* __restrict__ OUT)
{
    const int b = blockIdx.z, h = blockIdx.y;
    const int p0 = blockIdx.x * 32;
    const int y  = p0 / WW, x0 = p0 % WW;
    const float* Qb = QKV + ((size_t)b*3*DIM + h*CH)*HW;
    const float* Kb = Qb + (size_t)DIM*HW;
    const float* Vb = Qb + (size_t)2*DIM*HW;

    __shared__ float qs[CH][3][34];
    __shared__ float ks[CH][3][34];
    __shared__ float vs[CH][3][34];
    __shared__ float sato[CH][33];

    const int tid = threadIdx.y*32 + threadIdx.x;
    for (int i = tid; i < CH*3*34; i += 512) {
        int xi = i % 34; int rr = i / 34; int yi = rr % 3; int c = rr / 3;
        int yy = y + yi - 1, xx = x0 + xi - 1;
        bool ok = (yy >= 0 && yy < HH && xx >= 0 && xx < WW);
        int o = c*HW + yy*WW + xx;
        qs[c][yi][xi] = ok ? Qb[o] : 0.f;
        ks[c][yi][xi] = ok ? Kb[o] : 0.f;
        vs[c][yi][xi] = ok ? Vb[o] : 0.f;
    }
    __syncthreads();

    const int n = threadIdx.y, lx = threadIdx.x;
    float qr[9];
    #pragma unroll
    for (int t = 0; t < 9; t++) qr[t] = qs[n][t/3][lx + t%3] * 0.25f;

    float dots[CH], vsum[CH];
    #pragma unroll
    for (int m = 0; m < CH; m++) {
        float dv = 0.f, sv = 0.f;
        #pragma unroll
        for (int t = 0; t < 9; t++) {
            dv += qr[t] * ks[m][t/3][lx + t%3];
            sv += vs[m][t/3][lx + t%3];
        }
        dots[m] = dv; vsum[m] = sv;
    }
    float mx = dots[0];
    #pragma unroll
    for (int m = 1; m < CH; m++) mx = fmaxf(mx, dots[m]);
    float s = 0.f;
    #pragma unroll
    for (int m = 0; m < CH; m++) { dots[m] = __expf(dots[m]-mx); s += dots[m]; }
    float o = 0.f;
    #pragma unroll
    for (int m = 0; m < CH; m++) o += dots[m]*vsum[m];
    sato[n][lx] = o / s;
    __syncthreads();

    if (n < 8) {
        float v0 = sato[2*n][lx], v1 = sato[2*n+1][lx];
        uint32_t hi, lo; split2(v0, v1, hi, lo);
        OUT[(size_t)b*64*HW + (size_t)(h*8 + n)*HW + p0 + lx] = make_uint2(hi, lo);
    }
}

// ---------------- host orchestration ----------------
extern "C" void kernel_launch(void* const* d_in, const int* in_sizes, int n_in,
                              void* d_out, int out_size)
{
    const float* x      = (const float*)d_in[0];
    const float* w_in   = (const float*)d_in[1];
    const float* b_in   = (const float*)d_in[2];
    const float* conv_w = (const float*)d_in[3];
    const float* conv_b = (const float*)d_in[4];
    const float* bn_g   = (const float*)d_in[5];
    const float* bn_b   = (const float*)d_in[6];
    const float* qkv_w  = (const float*)d_in[7];
    const float* fc_w   = (const float*)d_in[8];
    const float* fc_b   = (const float*)d_in[9];
    const float* w_out  = (const float*)d_in[10];
    const float* b_out  = (const float*)d_in[11];
    float* out = (float*)d_out;

    float *p_t, *p_bn, *p_qkv;
    uint2 *p_hsp, *p_qsp, *p_asp, *p_cw, *p_qw, *p_fw, *p_wi, *p_wo;
    cudaGetSymbolAddress((void**)&p_t,    g_t);
    cudaGetSymbolAddress((void**)&p_bn,   g_bn);
    cudaGetSymbolAddress((void**)&p_qkv,  g_qkv);
    cudaGetSymbolAddress((void**)&p_hsp,  g_hsp);
    cudaGetSymbolAddress((void**)&p_qsp,  g_qsp);
    cudaGetSymbolAddress((void**)&p_asp,  g_asp);
    cudaGetSymbolAddress((void**)&p_cw,   g_cw);
    cudaGetSymbolAddress((void**)&p_qw,   g_qw);
    cudaGetSymbolAddress((void**)&p_fw,   g_fw);
    cudaGetSymbolAddress((void**)&p_wi,   g_wi);
    cudaGetSymbolAddress((void**)&p_wo,   g_wo);

    prep_all<<<(NC+NQ+NF+NI+NO + 255)/256, 256>>>(conv_w, qkv_w, fc_w, w_in, w_out);

    // input projection 64 -> 128, split output into g_hsp
    {
        dim3 g(HW/128, DIM/64, BATCH);
        gemm_bf3<<<g, 256>>>(p_wi, x, 0, b_in, nullptr, p_hsp, 1, DIM, CIN);
    }

    for (int i = 0; i < DEPTH; i++) {
        const int d = 1 << i;
        {
            dim3 g(2, HH, BATCH);
            conv3x3_bf3<<<g, 256>>>(p_hsp, p_cw + (size_t)i*9*64*DIM,
                                    conv_b + i*DIM, p_t, d);
        }
        {
            dim3 g((64*HW/4)/256, BATCH);
            bn_apply_relu<<<g, 256>>>(p_t, bn_g + i*DIM, bn_b + i*DIM, p_bn, p_qsp);
        }
        {
            dim3 g(HW/128, (3*DIM)/64, BATCH);
            gemm_bf3<<<g, 256>>>(p_qw + (size_t)i*64*3*DIM, p_qsp, 1, nullptr, nullptr,
                                 p_qkv, 0, 3*DIM, DIM);
        }
        {
            dim3 g(HW/32, HEADS, BATCH);
            dim3 blk(32, CH);
            attn_core<<<g, blk>>>(p_qkv, p_asp);
        }
        {
            dim3 g(HW/128, DIM/64, BATCH);
            gemm_bf3<<<g, 256>>>(p_fw + (size_t)i*64*DIM, p_asp, 1, fc_b + i*DIM, p_bn,
                                 p_hsp, 1, DIM, DIM);
        }
    }

    {
        dim3 g(HW/128, COUT/64, BATCH);
        gemm_bf3<<<g, 256>>>(p_wo, p_hsp, 1, b_out, nullptr, out, 0, COUT, DIM);
    }
}